// round 9
// baseline (speedup 1.0000x reference)
#include <cuda_runtime.h>
#include <cstdint>

#define BB 8
#define CC 20
#define NN 2048
#define NMS_T 0.45f
#define PRE_T 0.005f
#define SEG 32          // pair-kernel CTAs per batch
#define SEGCAP 16384    // edges per segment in global (32*16384 = 512K/batch total cap)
#define ECAP 9216       // resolve static-shared edge cap; exact global tail beyond
#define RT 256          // resolve threads

// Class-independent geometric suppression edges, per batch, per segment.
__device__ unsigned g_edges[BB][SEG * SEGCAP];
__device__ int g_cnt[BB][SEG];

// ---- Kernel A: brute-force triangle over original indices (proven-exact set) ----
// Static shared: 16KB + 16KB + 8KB + 4B.
__global__ __launch_bounds__(256)
void pairs_kernel(const float* __restrict__ bbs) {
    __shared__ float2 sx[NN];    // (x1, x2)
    __shared__ float2 sy[NN];    // (y1, y2)
    __shared__ float sar[NN];    // area
    __shared__ int scnt;

    const int b = blockIdx.y;
    const int seg = blockIdx.x;
    const int tid = threadIdx.x;
    const int wid = tid >> 5;
    const int lane = tid & 31;

    if (tid == 0) scnt = 0;

    const float4* gb = (const float4*)(bbs + (size_t)b * NN * 4);
    for (int i = tid; i < NN; i += 256) {
        float4 v = gb[i];
        sx[i] = make_float2(v.x, v.z);
        sy[i] = make_float2(v.y, v.w);
        sar[i] = __fmul_rn(fmaxf(__fsub_rn(v.z, v.x), 0.0f),
                           fmaxf(__fsub_rn(v.w, v.y), 0.0f));
    }
    __syncthreads();

    unsigned* el = &g_edges[b][seg * SEGCAP];

    // warp-per-pivot: 256 warps per batch stride the 2047 pivot rows
    const int warpGlobal = seg * 8 + wid;          // 0..255
    for (int i = warpGlobal; i < NN - 1; i += SEG * 8) {
        float2 px = sx[i];                         // broadcast LDS
        float2 py = sy[i];
        float pa = sar[i];
        for (int j = i + 1 + lane; j < NN; j += 32) {
            float2 qx = sx[j];
            float iw = __fsub_rn(fminf(px.y, qx.y), fmaxf(px.x, qx.x));
            if (iw <= 0.0f) continue;
            float2 qy = sy[j];
            float ih = __fsub_rn(fminf(py.y, qy.y), fmaxf(py.x, qy.x));
            if (ih <= 0.0f) continue;
            float inter = __fmul_rn(iw, ih);
            float den = fmaxf(__fsub_rn(__fadd_rn(pa, sar[j]), inter), 1e-12f);
            if (__fdiv_rn(inter, den) > NMS_T) {
                int pos = atomicAdd(&scnt, 1);
                if (pos < SEGCAP)
                    el[pos] = ((unsigned)i << 11) | (unsigned)j;
            }
        }
    }
    __syncthreads();
    if (tid == 0) g_cnt[b][seg] = min(scnt, SEGCAP);
}

// ---- Kernel B: per-class fixpoint; static-shared packed edges + exact global tail ----
// Static shared: 8KB + 36KB + ~1KB = 45.2KB.
__global__ __launch_bounds__(RT)
void resolve_kernel(const float* __restrict__ conf, float* __restrict__ out) {
    __shared__ unsigned cb[NN];          // conf bits (monotone key, conf >= 0)
    __shared__ unsigned epk[ECAP];       // packed (hi<<11)|lo edges
    __shared__ unsigned keep0m[64], aliveA[64], aliveB[64], supp[64];
    __shared__ int changed;

    const int bc = blockIdx.x;
    const int b = bc / CC;
    const int tid = threadIdx.x;

    const float* cp = conf + (size_t)bc * NN;
    for (int i = tid; i < NN; i += RT) {
        float v = cp[i];
        cb[i] = __float_as_uint(v);
        unsigned m = __ballot_sync(0xffffffffu, v > PRE_T);
        if ((tid & 31) == 0) { keep0m[i >> 5] = m; aliveA[i >> 5] = m; }
    }
    __syncthreads();

    // gather edges -> shared (up to ECAP), precompute rank direction
    // (conf desc, tie -> lower original index wins, matching stable argsort)
    int tot = 0;
    for (int s = 0; s < SEG; ++s) {
        int E = g_cnt[b][s];
        const unsigned* el = &g_edges[b][s * SEGCAP];
        for (int e = tid; e < E; e += RT) {
            int pos = tot + e;
            if (pos < ECAP) {
                unsigned u = el[e];
                int i = (int)(u >> 11), j = (int)(u & 2047u);
                unsigned bi = cb[i], bj = cb[j];
                int hi, lo;
                if (bi > bj || (bi == bj && i < j)) { hi = i; lo = j; }
                else                                { hi = j; lo = i; }
                epk[pos] = ((unsigned)hi << 11) | (unsigned)lo;
            }
        }
        tot += E;
    }
    const int stot = min(tot, ECAP);
    const bool has_tail = (tot > ECAP);
    __syncthreads();

    unsigned* cur = aliveA;
    unsigned* nxt = aliveB;

    for (int round = 0; round < NN; ++round) {
        __syncthreads();
        if (tid < 64) supp[tid] = 0;
        if (tid == 0) changed = 0;
        __syncthreads();

        // fast path: packed shared edges
        for (int e = tid; e < stot; e += RT) {
            unsigned p = epk[e];
            int hi = (int)(p >> 11), lo = (int)(p & 2047u);
            if ((cur[hi >> 5] >> (hi & 31)) & 1u)
                atomicOr(&supp[lo >> 5], 1u << (lo & 31));
        }

        // exact tail: edges beyond ECAP, straight from global raw lists
        if (has_tail) {
            int base = 0;
            for (int s = 0; s < SEG; ++s) {
                int E = g_cnt[b][s];
                const unsigned* el = &g_edges[b][s * SEGCAP];
                int start = ECAP - base; if (start < 0) start = 0;
                for (int e = start + tid; e < E; e += RT) {
                    unsigned u = el[e];
                    int i = (int)(u >> 11), j = (int)(u & 2047u);
                    unsigned bi = cb[i], bj = cb[j];
                    int hi, lo;
                    if (bi > bj || (bi == bj && i < j)) { hi = i; lo = j; }
                    else                                { hi = j; lo = i; }
                    if ((cur[hi >> 5] >> (hi & 31)) & 1u)
                        atomicOr(&supp[lo >> 5], 1u << (lo & 31));
                }
                base += E;
            }
        }
        __syncthreads();

        if (tid < 64) {
            unsigned na = keep0m[tid] & ~supp[tid];
            nxt[tid] = na;
            if (na != cur[tid]) changed = 1;   // benign race: all write 1
        }
        __syncthreads();

        int ch = changed;
        unsigned* t = cur; cur = nxt; nxt = t;
        if (!ch) break;
    }

    float* op = out + (size_t)bc * NN;
    for (int i = tid; i < NN; i += RT) {
        bool a = (cur[i >> 5] >> (i & 31)) & 1u;
        op[i] = a ? __uint_as_float(cb[i]) : 0.0f;
    }
}

extern "C" void kernel_launch(void* const* d_in, const int* in_sizes, int n_in,
                              void* d_out, int out_size) {
    const float* bbs;
    const float* conf;
    if (in_sizes[0] == BB * NN * 4) {
        bbs = (const float*)d_in[0];
        conf = (const float*)d_in[1];
    } else {
        bbs = (const float*)d_in[1];
        conf = (const float*)d_in[0];
    }
    float* out = (float*)d_out;

    pairs_kernel<<<dim3(SEG, BB), 256>>>(bbs);
    resolve_kernel<<<BB * CC, RT>>>(conf, out);
}

// round 11
// speedup vs baseline: 1.1947x; 1.1947x over previous
#include <cuda_runtime.h>
#include <cstdint>

#define BB 8
#define CC 20
#define NN 2048
#define NMS_T 0.45f
#define PRE_T 0.005f
#define SEG 64          // pair-kernel CTAs per batch (edge segments)
#define SEGCAP 8192     // edges per segment in global
#define ECAP 9216       // resolve static-shared edge cap; exact global tail beyond
#define RT 256          // resolve threads
#define NWARPS (SEG * 8)  // warps per batch in pairs kernel = 512

// Class-independent geometric suppression edges, per batch, per segment.
__device__ unsigned g_edges[BB][SEG * SEGCAP];
__device__ int g_cnt[BB][SEG];

__device__ __forceinline__ float box_area(float4 v) {
    return __fmul_rn(fmaxf(__fsub_rn(v.z, v.x), 0.0f),
                     fmaxf(__fsub_rn(v.w, v.y), 0.0f));
}

// ---- Kernel A: register-tiled all-pairs IoU (exact triangle partition) ----
__global__ __launch_bounds__(256)
void pairs_kernel(const float* __restrict__ bbs) {
    __shared__ int scnt;
    const int b = blockIdx.y;
    const int seg = blockIdx.x;
    const int tid = threadIdx.x;
    const int wid = tid >> 5;
    const int lane = tid & 31;

    if (tid == 0) scnt = 0;
    __syncthreads();

    const float4* gb = (const float4*)(bbs + (size_t)b * NN * 4);
    unsigned* el = &g_edges[b][seg * SEGCAP];

    const int w = seg * 8 + wid;          // 0..NWARPS-1 (warp-uniform)
    int rem = w;                          // offset of next owned tile in current row
    for (int ti = 0; ti < NN / 32; ++ti) {
        int rowLen = NN / 32 - ti;        // tiles (ti, ti..63)
        while (rem < rowLen) {            // warp-uniform condition
            int tj = ti + rem;
            // --- process 32x32 tile (ti, tj) ---
            int p = ti * 32 + lane;
            float4 P = gb[p];
            float pa = box_area(P);
            int qbase = tj * 32;
            float4 Q = gb[qbase + lane];
            float qa = box_area(Q);
            bool diag = (ti == tj);
            #pragma unroll 4
            for (int k = 0; k < 32; ++k) {
                float qx1 = __shfl_sync(0xffffffffu, Q.x, k);
                float qy1 = __shfl_sync(0xffffffffu, Q.y, k);
                float qx2 = __shfl_sync(0xffffffffu, Q.z, k);
                float qy2 = __shfl_sync(0xffffffffu, Q.w, k);
                float qak = __shfl_sync(0xffffffffu, qa, k);
                float iw = __fsub_rn(fminf(P.z, qx2), fmaxf(P.x, qx1));
                float ih = __fsub_rn(fminf(P.w, qy2), fmaxf(P.y, qy1));
                if (iw > 0.0f && ih > 0.0f) {
                    float inter = __fmul_rn(iw, ih);
                    float den = fmaxf(__fsub_rn(__fadd_rn(pa, qak), inter), 1e-12f);
                    if (__fdiv_rn(inter, den) > NMS_T) {
                        int q = qbase + k;
                        if (!diag || q > p) {
                            int pos = atomicAdd(&scnt, 1);
                            if (pos < SEGCAP)
                                el[pos] = ((unsigned)p << 11) | (unsigned)q;
                        }
                    }
                }
            }
            rem += NWARPS;
        }
        rem -= rowLen;
    }
    __syncthreads();
    if (tid == 0) g_cnt[b][seg] = min(scnt, SEGCAP);
}

// ---- Kernel B: per-class fixpoint; parallel gather + exact global tail ----
// Static shared ~46.6 KB.
__global__ __launch_bounds__(RT)
void resolve_kernel(const float* __restrict__ conf, float* __restrict__ out) {
    __shared__ unsigned cb[NN];          // conf bits (monotone key, conf >= 0)
    __shared__ unsigned epk[ECAP];       // packed (hi<<11)|lo edges
    __shared__ int segOff[SEG + 1];
    __shared__ int tmp[SEG];
    __shared__ unsigned keep0m[64], aliveA[64], aliveB[64], supp[64];
    __shared__ int changed;

    const int bc = blockIdx.x;
    const int b = bc / CC;
    const int tid = threadIdx.x;

    const float* cp = conf + (size_t)bc * NN;
    for (int i = tid; i < NN; i += RT) {
        float v = cp[i];
        cb[i] = __float_as_uint(v);
        unsigned m = __ballot_sync(0xffffffffu, v > PRE_T);
        if ((tid & 31) == 0) { keep0m[i >> 5] = m; aliveA[i >> 5] = m; }
    }
    // parallel segment-count load + inclusive scan (Hillis-Steele)
    if (tid < SEG) tmp[tid] = g_cnt[b][tid];
    __syncthreads();
    #pragma unroll
    for (int off = 1; off < SEG; off <<= 1) {
        int v = 0;
        if (tid < SEG) { v = tmp[tid]; if (tid >= off) v += tmp[tid - off]; }
        __syncthreads();
        if (tid < SEG) tmp[tid] = v;
        __syncthreads();
    }
    if (tid < SEG) segOff[tid + 1] = tmp[tid];
    if (tid == 0) segOff[0] = 0;
    __syncthreads();

    // gather edges -> shared (up to ECAP), precompute rank direction
    // (conf desc, tie -> lower original index wins, matching stable argsort)
    const int tot = segOff[SEG];
    for (int s = 0; s < SEG; ++s) {
        int base = segOff[s];
        int E = segOff[s + 1] - base;
        const unsigned* el = &g_edges[b][s * SEGCAP];
        for (int e = tid; e < E; e += RT) {
            int pos = base + e;
            if (pos < ECAP) {
                unsigned u = el[e];
                int i = (int)(u >> 11), j = (int)(u & 2047u);
                unsigned bi = cb[i], bj = cb[j];
                int hi, lo;
                if (bi > bj || (bi == bj && i < j)) { hi = i; lo = j; }
                else                                { hi = j; lo = i; }
                epk[pos] = ((unsigned)hi << 11) | (unsigned)lo;
            }
        }
    }
    const int stot = min(tot, ECAP);
    const bool has_tail = (tot > ECAP);
    __syncthreads();

    unsigned* cur = aliveA;
    unsigned* nxt = aliveB;

    for (int round = 0; round < NN; ++round) {
        __syncthreads();
        if (tid < 64) supp[tid] = 0;
        if (tid == 0) changed = 0;
        __syncthreads();

        // fast path: packed shared edges
        for (int e = tid; e < stot; e += RT) {
            unsigned p = epk[e];
            int hi = (int)(p >> 11), lo = (int)(p & 2047u);
            if ((cur[hi >> 5] >> (hi & 31)) & 1u)
                atomicOr(&supp[lo >> 5], 1u << (lo & 31));
        }

        // exact tail: edges beyond ECAP, straight from global raw lists
        if (has_tail) {
            for (int s = 0; s < SEG; ++s) {
                int base = segOff[s];
                int E = segOff[s + 1] - base;
                const unsigned* el = &g_edges[b][s * SEGCAP];
                int start = ECAP - base; if (start < 0) start = 0;
                for (int e = start + tid; e < E; e += RT) {
                    unsigned u = el[e];
                    int i = (int)(u >> 11), j = (int)(u & 2047u);
                    unsigned bi = cb[i], bj = cb[j];
                    int hi, lo;
                    if (bi > bj || (bi == bj && i < j)) { hi = i; lo = j; }
                    else                                { hi = j; lo = i; }
                    if ((cur[hi >> 5] >> (hi & 31)) & 1u)
                        atomicOr(&supp[lo >> 5], 1u << (lo & 31));
                }
            }
        }
        __syncthreads();

        if (tid < 64) {
            unsigned na = keep0m[tid] & ~supp[tid];
            nxt[tid] = na;
            if (na != cur[tid]) changed = 1;   // benign race: all write 1
        }
        __syncthreads();

        int ch = changed;
        unsigned* t = cur; cur = nxt; nxt = t;
        if (!ch) break;
    }

    float* op = out + (size_t)bc * NN;
    for (int i = tid; i < NN; i += RT) {
        bool a = (cur[i >> 5] >> (i & 31)) & 1u;
        op[i] = a ? __uint_as_float(cb[i]) : 0.0f;
    }
}

extern "C" void kernel_launch(void* const* d_in, const int* in_sizes, int n_in,
                              void* d_out, int out_size) {
    const float* bbs;
    const float* conf;
    if (in_sizes[0] == BB * NN * 4) {
        bbs = (const float*)d_in[0];
        conf = (const float*)d_in[1];
    } else {
        bbs = (const float*)d_in[1];
        conf = (const float*)d_in[0];
    }
    float* out = (float*)d_out;

    pairs_kernel<<<dim3(SEG, BB), 256>>>(bbs);
    resolve_kernel<<<BB * CC, RT>>>(conf, out);
}

// round 12
// speedup vs baseline: 1.6542x; 1.3846x over previous
#include <cuda_runtime.h>
#include <cstdint>

#define BB 8
#define CC 20
#define NN 2048
#define NMS_T 0.45f
#define PRE_T 0.005f
#define SEG 64          // pair-kernel CTAs per batch (edge segments)
#define SEGCAP 8192     // edges per segment in global
#define ECAP 24576      // resolve shared edge cap (96KB); exact flat tail beyond
#define RT 256          // resolve threads
#define NWARPS (SEG * 8)  // warps per batch in pairs kernel = 512

// Class-independent geometric suppression edges, per batch, per segment.
__device__ unsigned g_edges[BB][SEG * SEGCAP];
__device__ int g_cnt[BB][SEG];

__device__ __forceinline__ float box_area(float4 v) {
    return __fmul_rn(fmaxf(__fsub_rn(v.z, v.x), 0.0f),
                     fmaxf(__fsub_rn(v.w, v.y), 0.0f));
}

// ---- Kernel A: register-tiled all-pairs IoU (exact triangle partition) ----
__global__ __launch_bounds__(256)
void pairs_kernel(const float* __restrict__ bbs) {
    __shared__ int scnt;
    const int b = blockIdx.y;
    const int seg = blockIdx.x;
    const int tid = threadIdx.x;
    const int wid = tid >> 5;
    const int lane = tid & 31;

    if (tid == 0) scnt = 0;
    __syncthreads();

    const float4* gb = (const float4*)(bbs + (size_t)b * NN * 4);
    unsigned* el = &g_edges[b][seg * SEGCAP];

    const int w = seg * 8 + wid;          // 0..NWARPS-1 (warp-uniform)
    int rem = w;                          // offset of next owned tile in current row
    for (int ti = 0; ti < NN / 32; ++ti) {
        int rowLen = NN / 32 - ti;        // tiles (ti, ti..63)
        while (rem < rowLen) {            // warp-uniform condition
            int tj = ti + rem;
            int p = ti * 32 + lane;
            float4 P = gb[p];
            float pa = box_area(P);
            int qbase = tj * 32;
            float4 Q = gb[qbase + lane];
            float qa = box_area(Q);
            bool diag = (ti == tj);
            #pragma unroll 4
            for (int k = 0; k < 32; ++k) {
                float qx1 = __shfl_sync(0xffffffffu, Q.x, k);
                float qy1 = __shfl_sync(0xffffffffu, Q.y, k);
                float qx2 = __shfl_sync(0xffffffffu, Q.z, k);
                float qy2 = __shfl_sync(0xffffffffu, Q.w, k);
                float qak = __shfl_sync(0xffffffffu, qa, k);
                float iw = __fsub_rn(fminf(P.z, qx2), fmaxf(P.x, qx1));
                float ih = __fsub_rn(fminf(P.w, qy2), fmaxf(P.y, qy1));
                if (iw > 0.0f && ih > 0.0f) {
                    float inter = __fmul_rn(iw, ih);
                    float den = fmaxf(__fsub_rn(__fadd_rn(pa, qak), inter), 1e-12f);
                    if (__fdiv_rn(inter, den) > NMS_T) {
                        int q = qbase + k;
                        if (!diag || q > p) {
                            int pos = atomicAdd(&scnt, 1);
                            if (pos < SEGCAP)
                                el[pos] = ((unsigned)p << 11) | (unsigned)q;
                        }
                    }
                }
            }
            rem += NWARPS;
        }
        rem -= rowLen;
    }
    __syncthreads();
    if (tid == 0) g_cnt[b][seg] = min(scnt, SEGCAP);
}

// ---- Kernel B: per-class fixpoint; flat gather (binary search) + big shared cap ----
// Dynamic shared: cb 8KB + epk 96KB = 104KB -> 2 CTAs/SM, one wave of 160.
extern __shared__ unsigned dsm_u[];

__device__ __forceinline__ int find_seg(const int* segOff, int pos) {
    int lo = 0, hi = SEG;                 // invariant: segOff[lo] <= pos < segOff[hi]
    #pragma unroll
    for (int it = 0; it < 6; ++it) {      // 2^6 = SEG
        int mid = (lo + hi) >> 1;
        if (segOff[mid] <= pos) lo = mid; else hi = mid;
    }
    return lo;
}

__global__ __launch_bounds__(RT)
void resolve_kernel(const float* __restrict__ conf, float* __restrict__ out) {
    unsigned* cb = dsm_u;                // conf bits [NN]
    unsigned* epk = cb + NN;             // packed (hi<<11)|lo edges [ECAP]
    __shared__ int segOff[SEG + 1];
    __shared__ int tmp[SEG];
    __shared__ unsigned keep0m[64], aliveA[64], aliveB[64], supp[64];
    __shared__ int changed;

    const int bc = blockIdx.x;
    const int b = bc / CC;
    const int tid = threadIdx.x;

    const float* cp = conf + (size_t)bc * NN;
    for (int i = tid; i < NN; i += RT) {
        float v = cp[i];
        cb[i] = __float_as_uint(v);
        unsigned m = __ballot_sync(0xffffffffu, v > PRE_T);
        if ((tid & 31) == 0) { keep0m[i >> 5] = m; aliveA[i >> 5] = m; }
    }
    // parallel segment-count load + inclusive scan (Hillis-Steele)
    if (tid < SEG) tmp[tid] = g_cnt[b][tid];
    __syncthreads();
    #pragma unroll
    for (int off = 1; off < SEG; off <<= 1) {
        int v = 0;
        if (tid < SEG) { v = tmp[tid]; if (tid >= off) v += tmp[tid - off]; }
        __syncthreads();
        if (tid < SEG) tmp[tid] = v;
        __syncthreads();
    }
    if (tid < SEG) segOff[tid + 1] = tmp[tid];
    if (tid == 0) segOff[0] = 0;
    __syncthreads();

    const int tot = segOff[SEG];
    const int stot = min(tot, ECAP);
    const bool has_tail = (tot > ECAP);
    const unsigned* eb = g_edges[b];

    // flat gather: every edge load address-independent -> full MLP
    for (int pos = tid; pos < stot; pos += RT) {
        int s = find_seg(segOff, pos);
        unsigned u = eb[s * SEGCAP + (pos - segOff[s])];
        int i = (int)(u >> 11), j = (int)(u & 2047u);
        unsigned bi = cb[i], bj = cb[j];
        int hi, lo;
        // conf desc, tie -> lower original index wins (stable argsort)
        if (bi > bj || (bi == bj && i < j)) { hi = i; lo = j; }
        else                                { hi = j; lo = i; }
        epk[pos] = ((unsigned)hi << 11) | (unsigned)lo;
    }
    __syncthreads();

    unsigned* cur = aliveA;
    unsigned* nxt = aliveB;

    for (int round = 0; round < NN; ++round) {
        __syncthreads();
        if (tid < 64) supp[tid] = 0;
        if (tid == 0) changed = 0;
        __syncthreads();

        // fast path: packed shared edges
        for (int e = tid; e < stot; e += RT) {
            unsigned p = epk[e];
            int hi = (int)(p >> 11), lo = (int)(p & 2047u);
            if ((cur[hi >> 5] >> (hi & 31)) & 1u)
                atomicOr(&supp[lo >> 5], 1u << (lo & 31));
        }

        // exact tail: flat positions beyond ECAP, binary-searched, full MLP
        if (has_tail) {
            for (int pos = ECAP + tid; pos < tot; pos += RT) {
                int s = find_seg(segOff, pos);
                unsigned u = eb[s * SEGCAP + (pos - segOff[s])];
                int i = (int)(u >> 11), j = (int)(u & 2047u);
                unsigned bi = cb[i], bj = cb[j];
                int hi, lo;
                if (bi > bj || (bi == bj && i < j)) { hi = i; lo = j; }
                else                                { hi = j; lo = i; }
                if ((cur[hi >> 5] >> (hi & 31)) & 1u)
                    atomicOr(&supp[lo >> 5], 1u << (lo & 31));
            }
        }
        __syncthreads();

        if (tid < 64) {
            unsigned na = keep0m[tid] & ~supp[tid];
            nxt[tid] = na;
            if (na != cur[tid]) changed = 1;   // benign race: all write 1
        }
        __syncthreads();

        int ch = changed;
        unsigned* t = cur; cur = nxt; nxt = t;
        if (!ch) break;
    }

    float* op = out + (size_t)bc * NN;
    for (int i = tid; i < NN; i += RT) {
        bool a = (cur[i >> 5] >> (i & 31)) & 1u;
        op[i] = a ? __uint_as_float(cb[i]) : 0.0f;
    }
}

extern "C" void kernel_launch(void* const* d_in, const int* in_sizes, int n_in,
                              void* d_out, int out_size) {
    const float* bbs;
    const float* conf;
    if (in_sizes[0] == BB * NN * 4) {
        bbs = (const float*)d_in[0];
        conf = (const float*)d_in[1];
    } else {
        bbs = (const float*)d_in[1];
        conf = (const float*)d_in[0];
    }
    float* out = (float*)d_out;

    const int smemB = (NN + ECAP) * 4;   // 104 KB dynamic (R2-proven mechanism)
    cudaFuncSetAttribute(resolve_kernel,
        cudaFuncAttributeMaxDynamicSharedMemorySize, smemB);

    pairs_kernel<<<dim3(SEG, BB), 256>>>(bbs);
    resolve_kernel<<<BB * CC, RT, smemB>>>(conf, out);
}

// round 13
// speedup vs baseline: 1.7393x; 1.0515x over previous
#include <cuda_runtime.h>
#include <cstdint>

#define BB 8
#define CC 20
#define NN 2048
#define NMS_T 0.45f
#define PRE_T 0.005f
#define SEG 64          // pair-kernel CTAs per batch (edge segments)
#define SEGCAP 8192     // edges per segment in global
#define ECAP 24576      // resolve shared edge cap (96KB); exact flat tail beyond
#define RT 512          // resolve threads
#define NWARPS (SEG * 8)  // warps per batch in pairs kernel = 512

// Class-independent geometric suppression edges, per batch, per segment.
__device__ unsigned g_edges[BB][SEG * SEGCAP];
__device__ int g_cnt[BB][SEG];

__device__ __forceinline__ float box_area(float4 v) {
    return __fmul_rn(fmaxf(__fsub_rn(v.z, v.x), 0.0f),
                     fmaxf(__fsub_rn(v.w, v.y), 0.0f));
}

// ---- Kernel A: shared-staged tiled all-pairs IoU (exact triangle partition) ----
// Static shared: 32KB boxes + 8KB areas + 4B.
__global__ __launch_bounds__(256)
void pairs_kernel(const float* __restrict__ bbs) {
    __shared__ float4 sbox[NN];
    __shared__ float sarea[NN];
    __shared__ int scnt;

    const int b = blockIdx.y;
    const int seg = blockIdx.x;
    const int tid = threadIdx.x;
    const int wid = tid >> 5;
    const int lane = tid & 31;

    if (tid == 0) scnt = 0;

    const float4* gb = (const float4*)(bbs + (size_t)b * NN * 4);
    for (int i = tid; i < NN; i += 256) {
        float4 v = gb[i];
        sbox[i] = v;
        sarea[i] = box_area(v);
    }
    __syncthreads();

    unsigned* el = &g_edges[b][seg * SEGCAP];

    const int w = seg * 8 + wid;          // 0..NWARPS-1 (warp-uniform)
    int rem = w;                          // offset of next owned tile in current row
    for (int ti = 0; ti < NN / 32; ++ti) {
        int rowLen = NN / 32 - ti;        // tiles (ti, ti..63)
        while (rem < rowLen) {            // warp-uniform condition
            int tj = ti + rem;
            int p = ti * 32 + lane;
            float4 P = sbox[p];
            float pa = sarea[p];
            int qbase = tj * 32;
            bool diag = (ti == tj);
            #pragma unroll 8
            for (int k = 0; k < 32; ++k) {
                float4 Q = sbox[qbase + k];      // LDS broadcast
                float qa = sarea[qbase + k];     // LDS broadcast
                float iw = __fsub_rn(fminf(P.z, Q.z), fmaxf(P.x, Q.x));
                float ih = __fsub_rn(fminf(P.w, Q.w), fmaxf(P.y, Q.y));
                if (iw > 0.0f && ih > 0.0f) {
                    float inter = __fmul_rn(iw, ih);
                    float den = fmaxf(__fsub_rn(__fadd_rn(pa, qa), inter), 1e-12f);
                    if (__fdiv_rn(inter, den) > NMS_T) {
                        int q = qbase + k;
                        if (!diag || q > p) {
                            int pos = atomicAdd(&scnt, 1);
                            if (pos < SEGCAP)
                                el[pos] = ((unsigned)p << 11) | (unsigned)q;
                        }
                    }
                }
            }
            rem += NWARPS;
        }
        rem -= rowLen;
    }
    __syncthreads();
    if (tid == 0) g_cnt[b][seg] = min(scnt, SEGCAP);
}

// ---- Kernel B: per-class Gauss-Seidel fixpoint; flat gather, big shared cap ----
// Dynamic shared: cb 8KB + epk 96KB = 104KB -> 2 CTAs/SM.
extern __shared__ unsigned dsm_u[];

__device__ __forceinline__ int find_seg(const int* segOff, int pos) {
    int lo = 0, hi = SEG;
    #pragma unroll
    for (int it = 0; it < 6; ++it) {      // 2^6 = SEG
        int mid = (lo + hi) >> 1;
        if (segOff[mid] <= pos) lo = mid; else hi = mid;
    }
    return lo;
}

__global__ __launch_bounds__(RT)
void resolve_kernel(const float* __restrict__ conf, float* __restrict__ out) {
    unsigned* cb = dsm_u;                // conf bits [NN]
    unsigned* epk = cb + NN;             // packed (hi<<11)|lo edges [ECAP]
    __shared__ int segOff[SEG + 1];
    __shared__ int tmp[SEG];
    __shared__ unsigned keep0m[64], aliveA[64], aliveB[64], supp[64];
    __shared__ int changed;

    const int bc = blockIdx.x;
    const int b = bc / CC;
    const int tid = threadIdx.x;

    const float* cp = conf + (size_t)bc * NN;
    for (int i = tid; i < NN; i += RT) {
        float v = cp[i];
        cb[i] = __float_as_uint(v);
        unsigned m = __ballot_sync(0xffffffffu, v > PRE_T);
        if ((tid & 31) == 0) { keep0m[i >> 5] = m; aliveA[i >> 5] = m; }
    }
    // parallel segment-count load + inclusive scan (Hillis-Steele)
    if (tid < SEG) tmp[tid] = g_cnt[b][tid];
    __syncthreads();
    #pragma unroll
    for (int off = 1; off < SEG; off <<= 1) {
        int v = 0;
        if (tid < SEG) { v = tmp[tid]; if (tid >= off) v += tmp[tid - off]; }
        __syncthreads();
        if (tid < SEG) tmp[tid] = v;
        __syncthreads();
    }
    if (tid < SEG) segOff[tid + 1] = tmp[tid];
    if (tid == 0) segOff[0] = 0;
    __syncthreads();

    const int tot = segOff[SEG];
    const int stot = min(tot, ECAP);
    const bool has_tail = (tot > ECAP);
    const unsigned* eb = g_edges[b];

    // flat gather: address-independent edge loads -> full MLP
    for (int pos = tid; pos < stot; pos += RT) {
        int s = find_seg(segOff, pos);
        unsigned u = eb[s * SEGCAP + (pos - segOff[s])];
        int i = (int)(u >> 11), j = (int)(u & 2047u);
        unsigned bi = cb[i], bj = cb[j];
        int hi, lo;
        // conf desc, tie -> lower original index wins (stable argsort)
        if (bi > bj || (bi == bj && i < j)) { hi = i; lo = j; }
        else                                { hi = j; lo = i; }
        epk[pos] = ((unsigned)hi << 11) | (unsigned)lo;
    }
    __syncthreads();

    unsigned* cur = aliveA;
    unsigned* nxt = aliveB;

    for (int round = 0; round < NN; ++round) {
        __syncthreads();
        if (tid < 64) supp[tid] = 0;
        if (tid == 0) changed = 0;
        __syncthreads();

        // Gauss-Seidel: pivot alive = cur[hi] && !supp_partial[hi];
        // skip atomic when lo already marked. Converged round reproduces
        // Jacobi exactly (see proof in analysis), so fixpoint is unchanged.
        for (int e = tid; e < stot; e += RT) {
            unsigned p = epk[e];
            int hi = (int)(p >> 11), lo = (int)(p & 2047u);
            if ((supp[lo >> 5] >> (lo & 31)) & 1u) continue;   // already marked
            bool ha = ((cur[hi >> 5] >> (hi & 31)) & 1u) &&
                      !((supp[hi >> 5] >> (hi & 31)) & 1u);
            if (ha)
                atomicOr(&supp[lo >> 5], 1u << (lo & 31));
        }

        // exact tail: flat positions beyond ECAP, binary-searched, full MLP
        if (has_tail) {
            for (int pos = ECAP + tid; pos < tot; pos += RT) {
                int s = find_seg(segOff, pos);
                unsigned u = eb[s * SEGCAP + (pos - segOff[s])];
                int i = (int)(u >> 11), j = (int)(u & 2047u);
                unsigned bi = cb[i], bj = cb[j];
                int hi, lo;
                if (bi > bj || (bi == bj && i < j)) { hi = i; lo = j; }
                else                                { hi = j; lo = i; }
                if ((supp[lo >> 5] >> (lo & 31)) & 1u) continue;
                bool ha = ((cur[hi >> 5] >> (hi & 31)) & 1u) &&
                          !((supp[hi >> 5] >> (hi & 31)) & 1u);
                if (ha)
                    atomicOr(&supp[lo >> 5], 1u << (lo & 31));
            }
        }
        __syncthreads();

        if (tid < 64) {
            unsigned na = keep0m[tid] & ~supp[tid];
            nxt[tid] = na;
            if (na != cur[tid]) changed = 1;   // benign race: all write 1
        }
        __syncthreads();

        int ch = changed;
        unsigned* t = cur; cur = nxt; nxt = t;
        if (!ch) break;
    }

    float* op = out + (size_t)bc * NN;
    for (int i = tid; i < NN; i += RT) {
        bool a = (cur[i >> 5] >> (i & 31)) & 1u;
        op[i] = a ? __uint_as_float(cb[i]) : 0.0f;
    }
}

extern "C" void kernel_launch(void* const* d_in, const int* in_sizes, int n_in,
                              void* d_out, int out_size) {
    const float* bbs;
    const float* conf;
    if (in_sizes[0] == BB * NN * 4) {
        bbs = (const float*)d_in[0];
        conf = (const float*)d_in[1];
    } else {
        bbs = (const float*)d_in[1];
        conf = (const float*)d_in[0];
    }
    float* out = (float*)d_out;

    const int smemB = (NN + ECAP) * 4;   // 104 KB dynamic
    cudaFuncSetAttribute(resolve_kernel,
        cudaFuncAttributeMaxDynamicSharedMemorySize, smemB);

    pairs_kernel<<<dim3(SEG, BB), 256>>>(bbs);
    resolve_kernel<<<BB * CC, RT, smemB>>>(conf, out);
}

// round 14
// speedup vs baseline: 1.7617x; 1.0129x over previous
#include <cuda_runtime.h>
#include <cstdint>

#define BB 8
#define CC 20
#define NN 2048
#define NMS_T 0.45f
#define PRE_T 0.005f
#define SEG 64          // pair-kernel CTAs per batch (edge segments)
#define SEGCAP 8192     // edges per segment in global
#define ECAP 24576      // resolve shared edge cap (96KB); exact flat tail beyond
#define RT 512          // resolve threads
#define NBINS 128
#define NWARPS (SEG * 8)  // pairs warps per batch = 512

// Scratch: sorted-by-x1 per-batch arrays (deterministic order, shared by all CTAs)
__device__ float4 g_sbox[BB][NN];
__device__ float g_sar[BB][NN];
__device__ unsigned short g_sidx[BB][NN];
__device__ int g_binStart[BB][NBINS + 1];
// Class-independent geometric suppression edges, per batch, per segment.
__device__ unsigned g_edges[BB][SEG * SEGCAP];
__device__ int g_cnt[BB][SEG];

// monotone nondecreasing binning of x coords (x in [-0.105, 1.105])
__device__ __forceinline__ int xbin(float v) {
    int b = (int)floorf(__fmul_rn(__fadd_rn(v, 0.25f), 80.0f));
    return min(max(b, 0), NBINS - 1);
}

__device__ __forceinline__ float box_area(float4 v) {
    return __fmul_rn(fmaxf(__fsub_rn(v.z, v.x), 0.0f),
                     fmaxf(__fsub_rn(v.w, v.y), 0.0f));
}

// ---- Kernel 0: deterministic stable counting sort by x1-bin (1 CTA/batch) ----
// Positions derive ONLY from sums and lane arithmetic -> same permutation
// no matter the scheduling; every pairs-CTA sees one consistent global order.
__global__ __launch_bounds__(256)
void sort_kernel(const float* __restrict__ bbs) {
    __shared__ int hist[NBINS];
    __shared__ int binStartS[NBINS + 1];
    __shared__ int cnt[NBINS];
    __shared__ int warpHist[8][NBINS];

    const int b = blockIdx.x;
    const int tid = threadIdx.x;
    const int w = tid >> 5;
    const int lane = tid & 31;

    for (int i = tid; i < NBINS; i += 256) { hist[i] = 0; cnt[i] = 0; }
    __syncthreads();

    const float4* gb = (const float4*)(bbs + (size_t)b * NN * 4);
    for (int i = tid; i < NN; i += 256)
        atomicAdd(&hist[xbin(gb[i].x)], 1);   // sums only: deterministic
    __syncthreads();

    if (tid == 0) {
        int acc = 0;
        for (int k = 0; k < NBINS; ++k) { binStartS[k] = acc; acc += hist[k]; }
        binStartS[NBINS] = acc;   // == NN
    }
    __syncthreads();

    // 8 batches of 256 elements; rank within (bin) deterministically:
    // rank = cnt[bin] (prior batches) + sum of earlier warps' bin counts
    //        + lanes-below-with-same-bin (in-warp)
    for (int k = 0; k < 8; ++k) {
        int idx = k * 256 + tid;
        float4 v = gb[idx];
        int bin = xbin(v.x);

        for (int i = tid; i < 8 * NBINS; i += 256) ((int*)warpHist)[i] = 0;
        __syncthreads();

        unsigned same = __match_any_sync(0xffffffffu, bin);
        int lanesBelow = __popc(same & ((1u << lane) - 1u));
        if (lanesBelow == 0) warpHist[w][bin] = __popc(same);  // group leader
        __syncthreads();

        int before = cnt[bin] + lanesBelow;
        for (int w2 = 0; w2 < w; ++w2) before += warpHist[w2][bin];
        int pos = binStartS[bin] + before;

        g_sbox[b][pos] = v;
        g_sar[b][pos] = box_area(v);
        g_sidx[b][pos] = (unsigned short)idx;
        __syncthreads();

        for (int bb2 = tid; bb2 < NBINS; bb2 += 256) {
            int s = 0;
            #pragma unroll
            for (int w2 = 0; w2 < 8; ++w2) s += warpHist[w2][bb2];
            cnt[bb2] += s;
        }
        __syncthreads();
    }

    for (int i = tid; i < NBINS + 1; i += 256)
        g_binStart[b][i] = binStartS[i];
}

// ---- Kernel 1: windowed pair enumeration over the consistent sorted order ----
// Static shared: 32KB + 8KB + 4KB + 516B + 4B ~= 45.5KB.
__global__ __launch_bounds__(256)
void pairs_kernel() {
    __shared__ float4 sbox[NN];
    __shared__ float sar[NN];
    __shared__ unsigned short sidx[NN];
    __shared__ int sbinStart[NBINS + 1];
    __shared__ int scnt;

    const int b = blockIdx.y;
    const int seg = blockIdx.x;
    const int tid = threadIdx.x;
    const int wid = tid >> 5;
    const int lane = tid & 31;

    if (tid == 0) scnt = 0;
    for (int i = tid; i < NN; i += 256) {
        sbox[i] = g_sbox[b][i];
        sar[i] = g_sar[b][i];
        sidx[i] = g_sidx[b][i];
    }
    for (int i = tid; i < NBINS + 1; i += 256) sbinStart[i] = g_binStart[b][i];
    __syncthreads();

    unsigned* el = &g_edges[b][seg * SEGCAP];

    // warp-per-pivot over sorted positions; consistent order => exact coverage
    const int warpGlobal = seg * 8 + wid;      // 0..NWARPS-1
    for (int i = warpGlobal; i < NN - 1; i += NWARPS) {
        float4 p = sbox[i];                    // broadcast LDS
        float pa = sar[i];
        unsigned oi = sidx[i];
        int jmax = sbinStart[xbin(p.z) + 1];   // all j with x1_j < x2_i lie below
        for (int j = i + 1 + lane; j < jmax; j += 32) {
            float4 q = sbox[j];
            float iw = __fsub_rn(fminf(p.z, q.z), fmaxf(p.x, q.x));
            if (iw <= 0.0f) continue;
            float ih = __fsub_rn(fminf(p.w, q.w), fmaxf(p.y, q.y));
            if (ih <= 0.0f) continue;
            float inter = __fmul_rn(iw, ih);
            float den = fmaxf(__fsub_rn(__fadd_rn(pa, sar[j]), inter), 1e-12f);
            if (__fdiv_rn(inter, den) > NMS_T) {
                int pos = atomicAdd(&scnt, 1);
                if (pos < SEGCAP)
                    el[pos] = (oi << 11) | (unsigned)sidx[j];
            }
        }
    }
    __syncthreads();
    if (tid == 0) g_cnt[b][seg] = min(scnt, SEGCAP);
}

// ---- Kernel B: per-class Gauss-Seidel fixpoint (unchanged from R13) ----
extern __shared__ unsigned dsm_u[];

__device__ __forceinline__ int find_seg(const int* segOff, int pos) {
    int lo = 0, hi = SEG;
    #pragma unroll
    for (int it = 0; it < 6; ++it) {      // 2^6 = SEG
        int mid = (lo + hi) >> 1;
        if (segOff[mid] <= pos) lo = mid; else hi = mid;
    }
    return lo;
}

__global__ __launch_bounds__(RT)
void resolve_kernel(const float* __restrict__ conf, float* __restrict__ out) {
    unsigned* cb = dsm_u;                // conf bits [NN]
    unsigned* epk = cb + NN;             // packed (hi<<11)|lo edges [ECAP]
    __shared__ int segOff[SEG + 1];
    __shared__ int tmp[SEG];
    __shared__ unsigned keep0m[64], aliveA[64], aliveB[64], supp[64];
    __shared__ int changed;

    const int bc = blockIdx.x;
    const int b = bc / CC;
    const int tid = threadIdx.x;

    const float* cp = conf + (size_t)bc * NN;
    for (int i = tid; i < NN; i += RT) {
        float v = cp[i];
        cb[i] = __float_as_uint(v);
        unsigned m = __ballot_sync(0xffffffffu, v > PRE_T);
        if ((tid & 31) == 0) { keep0m[i >> 5] = m; aliveA[i >> 5] = m; }
    }
    if (tid < SEG) tmp[tid] = g_cnt[b][tid];
    __syncthreads();
    #pragma unroll
    for (int off = 1; off < SEG; off <<= 1) {
        int v = 0;
        if (tid < SEG) { v = tmp[tid]; if (tid >= off) v += tmp[tid - off]; }
        __syncthreads();
        if (tid < SEG) tmp[tid] = v;
        __syncthreads();
    }
    if (tid < SEG) segOff[tid + 1] = tmp[tid];
    if (tid == 0) segOff[0] = 0;
    __syncthreads();

    const int tot = segOff[SEG];
    const int stot = min(tot, ECAP);
    const bool has_tail = (tot > ECAP);
    const unsigned* eb = g_edges[b];

    for (int pos = tid; pos < stot; pos += RT) {
        int s = find_seg(segOff, pos);
        unsigned u = eb[s * SEGCAP + (pos - segOff[s])];
        int i = (int)(u >> 11), j = (int)(u & 2047u);
        unsigned bi = cb[i], bj = cb[j];
        int hi, lo;
        // conf desc, tie -> lower original index wins (stable argsort)
        if (bi > bj || (bi == bj && i < j)) { hi = i; lo = j; }
        else                                { hi = j; lo = i; }
        epk[pos] = ((unsigned)hi << 11) | (unsigned)lo;
    }
    __syncthreads();

    unsigned* cur = aliveA;
    unsigned* nxt = aliveB;

    for (int round = 0; round < NN; ++round) {
        __syncthreads();
        if (tid < 64) supp[tid] = 0;
        if (tid == 0) changed = 0;
        __syncthreads();

        // Gauss-Seidel: converged round reproduces Jacobi exactly -> same
        // unique fixpoint (= greedy NMS); within-round reads only accelerate.
        for (int e = tid; e < stot; e += RT) {
            unsigned p = epk[e];
            int hi = (int)(p >> 11), lo = (int)(p & 2047u);
            if ((supp[lo >> 5] >> (lo & 31)) & 1u) continue;
            bool ha = ((cur[hi >> 5] >> (hi & 31)) & 1u) &&
                      !((supp[hi >> 5] >> (hi & 31)) & 1u);
            if (ha)
                atomicOr(&supp[lo >> 5], 1u << (lo & 31));
        }

        if (has_tail) {
            for (int pos = ECAP + tid; pos < tot; pos += RT) {
                int s = find_seg(segOff, pos);
                unsigned u = eb[s * SEGCAP + (pos - segOff[s])];
                int i = (int)(u >> 11), j = (int)(u & 2047u);
                unsigned bi = cb[i], bj = cb[j];
                int hi, lo;
                if (bi > bj || (bi == bj && i < j)) { hi = i; lo = j; }
                else                                { hi = j; lo = i; }
                if ((supp[lo >> 5] >> (lo & 31)) & 1u) continue;
                bool ha = ((cur[hi >> 5] >> (hi & 31)) & 1u) &&
                          !((supp[hi >> 5] >> (hi & 31)) & 1u);
                if (ha)
                    atomicOr(&supp[lo >> 5], 1u << (lo & 31));
            }
        }
        __syncthreads();

        if (tid < 64) {
            unsigned na = keep0m[tid] & ~supp[tid];
            nxt[tid] = na;
            if (na != cur[tid]) changed = 1;   // benign race: all write 1
        }
        __syncthreads();

        int ch = changed;
        unsigned* t = cur; cur = nxt; nxt = t;
        if (!ch) break;
    }

    float* op = out + (size_t)bc * NN;
    for (int i = tid; i < NN; i += RT) {
        bool a = (cur[i >> 5] >> (i & 31)) & 1u;
        op[i] = a ? __uint_as_float(cb[i]) : 0.0f;
    }
}

extern "C" void kernel_launch(void* const* d_in, const int* in_sizes, int n_in,
                              void* d_out, int out_size) {
    const float* bbs;
    const float* conf;
    if (in_sizes[0] == BB * NN * 4) {
        bbs = (const float*)d_in[0];
        conf = (const float*)d_in[1];
    } else {
        bbs = (const float*)d_in[1];
        conf = (const float*)d_in[0];
    }
    float* out = (float*)d_out;

    const int smemB = (NN + ECAP) * 4;   // 104 KB dynamic
    cudaFuncSetAttribute(resolve_kernel,
        cudaFuncAttributeMaxDynamicSharedMemorySize, smemB);

    sort_kernel<<<BB, 256>>>(bbs);
    pairs_kernel<<<dim3(SEG, BB), 256>>>();
    resolve_kernel<<<BB * CC, RT, smemB>>>(conf, out);
}

// round 15
// speedup vs baseline: 1.9020x; 1.0797x over previous
#include <cuda_runtime.h>
#include <cstdint>

#define BB 8
#define CC 20
#define NN 2048
#define NMS_T 0.45f
#define PRE_T 0.005f
#define SEG 64          // pair-kernel CTAs per batch (edge segments)
#define SEGCAP 8192     // edges per segment in global
#define ECAP 24576      // resolve shared edge cap (96KB); exact flat tail beyond
#define RT 512          // resolve threads
#define NBINS 128
#define NCHUNK (NN / 32)   // 64 chunks of 32 elements
#define NWARPS (SEG * 8)   // pairs warps per batch = 512

// Scratch: sorted-by-x1 per-batch arrays (deterministic order, shared by all CTAs)
__device__ float4 g_sbox[BB][NN];
__device__ float g_sar[BB][NN];
__device__ unsigned short g_sidx[BB][NN];
__device__ int g_binStart[BB][NBINS + 1];
// Class-independent geometric suppression edges, per batch, per segment.
__device__ unsigned g_edges[BB][SEG * SEGCAP];
__device__ int g_cnt[BB][SEG];

// monotone nondecreasing binning of x coords (x in [-0.105, 1.105])
__device__ __forceinline__ int xbin(float v) {
    int b = (int)floorf(__fmul_rn(__fadd_rn(v, 0.25f), 80.0f));
    return min(max(b, 0), NBINS - 1);
}

__device__ __forceinline__ float box_area(float4 v) {
    return __fmul_rn(fmaxf(__fsub_rn(v.z, v.x), 0.0f),
                     fmaxf(__fsub_rn(v.w, v.y), 0.0f));
}

// ---- Kernel 0: deterministic stable counting sort, 3-pass chunk-histogram ----
// All positions derive from sums + lane arithmetic only -> one fixed
// permutation regardless of scheduling. Static shared ~37KB.
__global__ __launch_bounds__(512)
void sort_kernel(const float* __restrict__ bbs) {
    __shared__ int chunkHist[NCHUNK][NBINS];      // 32KB: counts -> exclusive prefix
    __shared__ int binStartS[NBINS + 1];
    __shared__ unsigned char sbin[NN];            // bin per element
    __shared__ unsigned char slb[NN];             // lanes-below per element

    const int b = blockIdx.x;
    const int tid = threadIdx.x;
    const int lane = tid & 31;

    // zero chunk histograms (one pass)
    for (int i = tid; i < NCHUNK * NBINS; i += 512) ((int*)chunkHist)[i] = 0;
    __syncthreads();

    const float4* gb = (const float4*)(bbs + (size_t)b * NN * 4);

    // Pass 1: per-chunk bin counts via match_any; cache bin + lanesBelow
    for (int c = tid >> 5; c < NCHUNK; c += 16) {       // warp per chunk
        int idx = c * 32 + lane;
        int bin = xbin(gb[idx].x);
        unsigned same = __match_any_sync(0xffffffffu, bin);
        int lb = __popc(same & ((1u << lane) - 1u));
        sbin[idx] = (unsigned char)bin;
        slb[idx] = (unsigned char)lb;
        if (lb == 0) chunkHist[c][bin] = __popc(same);  // group leader
    }
    __syncthreads();

    // Pass 2a: per-bin exclusive prefix over chunks (parallel across 128 bins)
    if (tid < NBINS) {
        int running = 0;
        #pragma unroll 8
        for (int c = 0; c < NCHUNK; ++c) {
            int t = chunkHist[c][tid];
            chunkHist[c][tid] = running;
            running += t;
        }
        binStartS[tid] = running;   // total per bin (temporarily)
    }
    __syncthreads();

    // Pass 2b: scan bins -> binStart
    if (tid == 0) {
        int acc = 0;
        #pragma unroll 8
        for (int k = 0; k < NBINS; ++k) {
            int t = binStartS[k];
            binStartS[k] = acc;
            acc += t;
        }
        binStartS[NBINS] = acc;    // == NN
    }
    __syncthreads();

    // Pass 3: scatter to deterministic positions
    for (int idx = tid; idx < NN; idx += 512) {
        int bin = sbin[idx];
        int c = idx >> 5;
        int pos = binStartS[bin] + chunkHist[c][bin] + slb[idx];
        float4 v = gb[idx];
        g_sbox[b][pos] = v;
        g_sar[b][pos] = box_area(v);
        g_sidx[b][pos] = (unsigned short)idx;
    }
    for (int i = tid; i < NBINS + 1; i += 512)
        g_binStart[b][i] = binStartS[i];
}

// ---- Kernel 1: windowed pair enumeration over the consistent sorted order ----
// Static shared: 32KB + 8KB + 4KB + 516B + 4B ~= 45.5KB.
__global__ __launch_bounds__(256)
void pairs_kernel() {
    __shared__ float4 sbox[NN];
    __shared__ float sar[NN];
    __shared__ unsigned short sidx[NN];
    __shared__ int sbinStart[NBINS + 1];
    __shared__ int scnt;

    const int b = blockIdx.y;
    const int seg = blockIdx.x;
    const int tid = threadIdx.x;
    const int wid = tid >> 5;
    const int lane = tid & 31;

    if (tid == 0) scnt = 0;
    for (int i = tid; i < NN; i += 256) {
        sbox[i] = g_sbox[b][i];
        sar[i] = g_sar[b][i];
        sidx[i] = g_sidx[b][i];
    }
    for (int i = tid; i < NBINS + 1; i += 256) sbinStart[i] = g_binStart[b][i];
    __syncthreads();

    unsigned* el = &g_edges[b][seg * SEGCAP];

    // warp-per-pivot over sorted positions; consistent order => exact coverage
    const int warpGlobal = seg * 8 + wid;      // 0..NWARPS-1
    for (int i = warpGlobal; i < NN - 1; i += NWARPS) {
        float4 p = sbox[i];                    // broadcast LDS
        float pa = sar[i];
        unsigned oi = sidx[i];
        int jmax = sbinStart[xbin(p.z) + 1];   // all j with x1_j < x2_i lie below
        for (int j = i + 1 + lane; j < jmax; j += 32) {
            float4 q = sbox[j];
            float iw = __fsub_rn(fminf(p.z, q.z), fmaxf(p.x, q.x));
            if (iw <= 0.0f) continue;
            float ih = __fsub_rn(fminf(p.w, q.w), fmaxf(p.y, q.y));
            if (ih <= 0.0f) continue;
            float inter = __fmul_rn(iw, ih);
            float den = fmaxf(__fsub_rn(__fadd_rn(pa, sar[j]), inter), 1e-12f);
            if (__fdiv_rn(inter, den) > NMS_T) {
                int pos = atomicAdd(&scnt, 1);
                if (pos < SEGCAP)
                    el[pos] = (oi << 11) | (unsigned)sidx[j];
            }
        }
    }
    __syncthreads();
    if (tid == 0) g_cnt[b][seg] = min(scnt, SEGCAP);
}

// ---- Kernel B: per-class Gauss-Seidel fixpoint (unchanged from R13/14) ----
extern __shared__ unsigned dsm_u[];

__device__ __forceinline__ int find_seg(const int* segOff, int pos) {
    int lo = 0, hi = SEG;
    #pragma unroll
    for (int it = 0; it < 6; ++it) {      // 2^6 = SEG
        int mid = (lo + hi) >> 1;
        if (segOff[mid] <= pos) lo = mid; else hi = mid;
    }
    return lo;
}

__global__ __launch_bounds__(RT)
void resolve_kernel(const float* __restrict__ conf, float* __restrict__ out) {
    unsigned* cb = dsm_u;                // conf bits [NN]
    unsigned* epk = cb + NN;             // packed (hi<<11)|lo edges [ECAP]
    __shared__ int segOff[SEG + 1];
    __shared__ int tmp[SEG];
    __shared__ unsigned keep0m[64], aliveA[64], aliveB[64], supp[64];
    __shared__ int changed;

    const int bc = blockIdx.x;
    const int b = bc / CC;
    const int tid = threadIdx.x;

    const float* cp = conf + (size_t)bc * NN;
    for (int i = tid; i < NN; i += RT) {
        float v = cp[i];
        cb[i] = __float_as_uint(v);
        unsigned m = __ballot_sync(0xffffffffu, v > PRE_T);
        if ((tid & 31) == 0) { keep0m[i >> 5] = m; aliveA[i >> 5] = m; }
    }
    if (tid < SEG) tmp[tid] = g_cnt[b][tid];
    __syncthreads();
    #pragma unroll
    for (int off = 1; off < SEG; off <<= 1) {
        int v = 0;
        if (tid < SEG) { v = tmp[tid]; if (tid >= off) v += tmp[tid - off]; }
        __syncthreads();
        if (tid < SEG) tmp[tid] = v;
        __syncthreads();
    }
    if (tid < SEG) segOff[tid + 1] = tmp[tid];
    if (tid == 0) segOff[0] = 0;
    __syncthreads();

    const int tot = segOff[SEG];
    const int stot = min(tot, ECAP);
    const bool has_tail = (tot > ECAP);
    const unsigned* eb = g_edges[b];

    for (int pos = tid; pos < stot; pos += RT) {
        int s = find_seg(segOff, pos);
        unsigned u = eb[s * SEGCAP + (pos - segOff[s])];
        int i = (int)(u >> 11), j = (int)(u & 2047u);
        unsigned bi = cb[i], bj = cb[j];
        int hi, lo;
        // conf desc, tie -> lower original index wins (stable argsort)
        if (bi > bj || (bi == bj && i < j)) { hi = i; lo = j; }
        else                                { hi = j; lo = i; }
        epk[pos] = ((unsigned)hi << 11) | (unsigned)lo;
    }
    __syncthreads();

    unsigned* cur = aliveA;
    unsigned* nxt = aliveB;

    for (int round = 0; round < NN; ++round) {
        __syncthreads();
        if (tid < 64) supp[tid] = 0;
        if (tid == 0) changed = 0;
        __syncthreads();

        // Gauss-Seidel: converged round reproduces Jacobi exactly -> same
        // unique fixpoint (= greedy NMS); within-round reads only accelerate.
        for (int e = tid; e < stot; e += RT) {
            unsigned p = epk[e];
            int hi = (int)(p >> 11), lo = (int)(p & 2047u);
            if ((supp[lo >> 5] >> (lo & 31)) & 1u) continue;
            bool ha = ((cur[hi >> 5] >> (hi & 31)) & 1u) &&
                      !((supp[hi >> 5] >> (hi & 31)) & 1u);
            if (ha)
                atomicOr(&supp[lo >> 5], 1u << (lo & 31));
        }

        if (has_tail) {
            for (int pos = ECAP + tid; pos < tot; pos += RT) {
                int s = find_seg(segOff, pos);
                unsigned u = eb[s * SEGCAP + (pos - segOff[s])];
                int i = (int)(u >> 11), j = (int)(u & 2047u);
                unsigned bi = cb[i], bj = cb[j];
                int hi, lo;
                if (bi > bj || (bi == bj && i < j)) { hi = i; lo = j; }
                else                                { hi = j; lo = i; }
                if ((supp[lo >> 5] >> (lo & 31)) & 1u) continue;
                bool ha = ((cur[hi >> 5] >> (hi & 31)) & 1u) &&
                          !((supp[hi >> 5] >> (hi & 31)) & 1u);
                if (ha)
                    atomicOr(&supp[lo >> 5], 1u << (lo & 31));
            }
        }
        __syncthreads();

        if (tid < 64) {
            unsigned na = keep0m[tid] & ~supp[tid];
            nxt[tid] = na;
            if (na != cur[tid]) changed = 1;   // benign race: all write 1
        }
        __syncthreads();

        int ch = changed;
        unsigned* t = cur; cur = nxt; nxt = t;
        if (!ch) break;
    }

    float* op = out + (size_t)bc * NN;
    for (int i = tid; i < NN; i += RT) {
        bool a = (cur[i >> 5] >> (i & 31)) & 1u;
        op[i] = a ? __uint_as_float(cb[i]) : 0.0f;
    }
}

extern "C" void kernel_launch(void* const* d_in, const int* in_sizes, int n_in,
                              void* d_out, int out_size) {
    const float* bbs;
    const float* conf;
    if (in_sizes[0] == BB * NN * 4) {
        bbs = (const float*)d_in[0];
        conf = (const float*)d_in[1];
    } else {
        bbs = (const float*)d_in[1];
        conf = (const float*)d_in[0];
    }
    float* out = (float*)d_out;

    const int smemB = (NN + ECAP) * 4;   // 104 KB dynamic
    cudaFuncSetAttribute(resolve_kernel,
        cudaFuncAttributeMaxDynamicSharedMemorySize, smemB);

    sort_kernel<<<BB, 512>>>(bbs);
    pairs_kernel<<<dim3(SEG, BB), 256>>>();
    resolve_kernel<<<BB * CC, RT, smemB>>>(conf, out);
}